// round 13
// baseline (speedup 1.0000x reference)
#include <cuda_runtime.h>
#include <cuda_fp16.h>
#include <stdint.h>
#include <math.h>

// ---------------- problem constants ----------------
#define BATCH 8
#define CIN   128
#define COUT  256
#define HH    64
#define WW    64
#define HWSZ  4096
#define KK9   9
#define CK    1152          // CIN*KK9
#define NOC   27            // 18 offset + 9 modulation channels
#define ROWS  (BATCH*HWSZ)  // 32768

// ---------------- scratch ------------------------------------------------
__device__ __half g_xTh[BATCH * HWSZ * CIN];        // x channels-last fp16
__device__ float  g_off[BATCH * NOC * HWSZ];        // offsets + modulation(sigmoid)
__device__ __half g_Wch[32 * CK];                   // conv weights fp16, padded to 32 oc
__device__ __half g_Wh [COUT * CK];                 // deform weights fp16
__device__ __half g_V  [(size_t)ROWS * CK];         // sampled*mod fp16
__device__ float  g_outT[(size_t)ROWS * COUT];
__device__ float  g_part[512 * 512];
__device__ float  g_scale[COUT];
__device__ float  g_shift[COUT];

// ---------------- ptx helpers (plain sm_80+ PTX only) --------------------
__device__ __forceinline__ uint32_t smem_u32(const void* p) {
    uint32_t a;
    asm("{ .reg .u64 t; cvta.to.shared.u64 t, %1; cvt.u32.u64 %0, t; }"
        : "=r"(a) : "l"(p));
    return a;
}
__device__ __forceinline__ void cp16(uint32_t dst, const void* src) {
    asm volatile("cp.async.cg.shared.global [%0], [%1], 16;" :: "r"(dst), "l"(src));
}
__device__ __forceinline__ void cp16z(uint32_t dst, const void* src, uint32_t sz) {
    asm volatile("cp.async.cg.shared.global [%0], [%1], 16, %2;"
                 :: "r"(dst), "l"(src), "r"(sz));
}
__device__ __forceinline__ void cp_commit() {
    asm volatile("cp.async.commit_group;" ::: "memory");
}
template <int N>
__device__ __forceinline__ void cp_wait() {
    asm volatile("cp.async.wait_group %0;" :: "n"(N) : "memory");
}
__device__ __forceinline__ void ldm_x4(uint32_t* r, uint32_t addr) {
    asm volatile("ldmatrix.sync.aligned.m8n8.x4.shared.b16 {%0,%1,%2,%3}, [%4];"
        : "=r"(r[0]), "=r"(r[1]), "=r"(r[2]), "=r"(r[3]) : "r"(addr));
}
__device__ __forceinline__ void mma_f16(float* d, const uint32_t* a,
                                        uint32_t b0, uint32_t b1) {
    asm volatile(
        "mma.sync.aligned.m16n8k16.row.col.f32.f16.f16.f32 "
        "{%0,%1,%2,%3}, {%4,%5,%6,%7}, {%8,%9}, {%0,%1,%2,%3};"
        : "+f"(d[0]), "+f"(d[1]), "+f"(d[2]), "+f"(d[3])
        : "r"(a[0]), "r"(a[1]), "r"(a[2]), "r"(a[3]), "r"(b0), "r"(b1));
}

// ---------------- 1) prep: transpose x -> fp16 channels-last + weights ---
__global__ void k_prep(const float* __restrict__ x,
                       const float* __restrict__ w_dc,
                       const float* __restrict__ w_off,
                       const float* __restrict__ w_mod) {
    if (blockIdx.z < 8) {
        __shared__ float tile[32][33];
        int b   = blockIdx.z;
        int hw0 = blockIdx.x * 32;
        int c0  = blockIdx.y * 32;
        int tx = threadIdx.x, ty = threadIdx.y;
        #pragma unroll
        for (int j = 0; j < 4; j++) {
            int c = c0 + ty + j * 8;
            tile[ty + j * 8][tx] = x[((b * CIN) + c) * HWSZ + hw0 + tx];
        }
        __syncthreads();
        #pragma unroll
        for (int j = 0; j < 4; j++) {
            int hw = hw0 + ty + j * 8;
            size_t o = ((size_t)(b * HWSZ) + hw) * CIN + c0 + tx;
            g_xTh[o] = __float2half(tile[tx][ty + j * 8]);
        }
    } else {
        const int NWP  = COUT * CK;         // 294912
        const int NWC2 = 32 * CK;           // 36864
        int t = threadIdx.y * 32 + threadIdx.x;
        int gidx = (blockIdx.y * 128 + blockIdx.x) * 256 + t;
        for (int idx = gidx; idx < NWP + NWC2; idx += 512 * 256) {
            if (idx < NWP) {
                int o  = idx / CK;
                int r  = idx - o * CK;
                int kk = r >> 7;
                int c  = r & 127;
                g_Wh[idx] = __float2half(w_dc[(o * CIN + c) * KK9 + kk]);
            } else {
                int j  = idx - NWP;
                int oc = j / CK;
                int r  = j - oc * CK;
                int kk = r >> 7;
                int c  = r & 127;
                float v = 0.f;
                if (oc < 18)      v = w_off[(oc * CIN + c) * KK9 + kk];
                else if (oc < 27) v = w_mod[((oc - 18) * CIN + c) * KK9 + kk];
                g_Wch[j] = __float2half(v);
            }
        }
    }
}

// ---------------- 2) conv offsets/mod via tensor cores --------------------
#define RCWB   80
#define A2_B   (128 * RCWB)                 // 10240
#define B2_B   (32 * RCWB)                  // 2560
#define CSTG   (A2_B + B2_B)                // 12800
#define CONV_SMEM (2 * CSTG)                // 25600

__device__ __forceinline__ void conv_load_stage(uint32_t buf, int cn,
                                                int rowBlk, int tid) {
    int kk  = cn >> 2;
    int c0k = (cn & 3) * 32;
    int dy = kk / 3 - 1;
    int dx = kk % 3 - 1;
    {
        int row  = tid >> 1;
        int half = tid & 1;
        int pix = rowBlk * 128 + row;
        int b = pix >> 12;
        int h = (pix >> 6) & 63;
        int w = pix & 63;
        int h2 = h + dy, w2 = w + dx;
        bool valid = ((unsigned)h2 < 64u) & ((unsigned)w2 < 64u);
        size_t srcoff = valid
            ? (((size_t)b * HWSZ + h2 * 64 + w2) * CIN + c0k) * 2 : 0;
        uint32_t sz = valid ? 16u : 0u;
        const char* src = (const char*)g_xTh + srcoff + half * 32;
        uint32_t dst = buf + row * RCWB + half * 32;
        cp16z(dst,      src,      sz);
        cp16z(dst + 16, src + 16, sz);
    }
    if (tid < 128) {
        int row = tid >> 2;
        int q   = tid & 3;
        const char* src = (const char*)g_Wch + ((size_t)row * CK + cn * 32) * 2 + q * 16;
        cp16(buf + A2_B + row * RCWB + q * 16, src);
    }
}

__global__ void __launch_bounds__(256) k_conv_tc(const float* __restrict__ b_off,
                                                 const float* __restrict__ b_mod) {
    extern __shared__ __align__(128) char sm[];
    const uint32_t base = smem_u32(sm);
    const int tid  = threadIdx.x;
    const int lane = tid & 31;
    const int wid  = tid >> 5;
    const int rowBlk = blockIdx.x;

    const int lrow  = lane & 15;
    const int lhalf = (lane >> 4) * 16;

    float acc[4][4];
    #pragma unroll
    for (int i = 0; i < 4; i++)
        #pragma unroll
        for (int q = 0; q < 4; q++) acc[i][q] = 0.f;

    conv_load_stage(base, 0, rowBlk, tid);
    cp_commit();

    for (int cn = 0; cn < 36; cn++) {
        int s = cn & 1;
        if (cn + 1 < 36) {
            conv_load_stage(base + ((cn + 1) & 1) * CSTG, cn + 1, rowBlk, tid);
            cp_commit();
            cp_wait<1>();
        } else {
            cp_wait<0>();
        }
        __syncthreads();

        uint32_t bufA = base + s * CSTG;
        uint32_t bufB = bufA + A2_B;

        #pragma unroll
        for (int ks = 0; ks < 2; ks++) {
            uint32_t a[4];
            ldm_x4(a, bufA + (uint32_t)(wid * 16 + lrow) * RCWB + ks * 32 + lhalf);
            uint32_t bfr[2][4];
            #pragma unroll
            for (int pr = 0; pr < 2; pr++)
                ldm_x4(bfr[pr], bufB + (uint32_t)(pr * 16 + lrow) * RCWB + ks * 32 + lhalf);
            #pragma unroll
            for (int pr = 0; pr < 2; pr++) {
                mma_f16(acc[2 * pr],     a, bfr[pr][0], bfr[pr][2]);
                mma_f16(acc[2 * pr + 1], a, bfr[pr][1], bfr[pr][3]);
            }
        }
        __syncthreads();
    }

    int pix0 = rowBlk * 128 + wid * 16 + (lane >> 2);
    int b = pix0 >> 12;
    #pragma unroll
    for (int ni = 0; ni < 4; ni++) {
        #pragma unroll
        for (int q = 0; q < 4; q++) {
            int oc = ni * 8 + (lane & 3) * 2 + (q & 1);
            if (oc >= NOC) continue;
            int pix = pix0 + (q >> 1) * 8;
            float bias = (oc < 18) ? b_off[oc] : b_mod[oc - 18];
            float v = acc[ni][q] + bias;
            if (oc >= 18) v = 1.f / (1.f + __expf(-v));
            g_off[((size_t)b * NOC + oc) * HWSZ + (pix & 4095)] = v;
        }
    }
}

// ---------------- 3) bilinear sampling (fp16 src, 8 ch/thread) -----------
__global__ void __launch_bounds__(256) k_sample() {
    int tx  = threadIdx.x;                  // 0..15 channel octet
    int pos = blockIdx.x * 16 + threadIdx.y;
    int kk  = blockIdx.y;
    int b   = blockIdx.z;
    int h = pos >> 6, w = pos & 63;

    const float* offb = g_off + (b * NOC) * HWSZ;
    float dy = offb[(2 * kk)     * HWSZ + pos];
    float dx = offb[(2 * kk + 1) * HWSZ + pos];
    float m  = offb[(18 + kk)    * HWSZ + pos];

    float py = dy + (float)(h - 1 + kk / 3);
    float px = dx + (float)(w - 1 + kk % 3);
    float fy = floorf(py), fx = floorf(px);
    int y0 = (int)fy, x0 = (int)fx;
    float wy1 = py - fy, wx1 = px - fx;
    float wy0 = 1.f - wy1, wx0 = 1.f - wx1;

    const uint4* xb = (const uint4*)g_xTh + (size_t)(b * HWSZ) * 16;
    float acc[8];
    #pragma unroll
    for (int i = 0; i < 8; i++) acc[i] = 0.f;

    #pragma unroll
    for (int cn = 0; cn < 4; cn++) {
        int yi = y0 + (cn >> 1);
        int xi = x0 + (cn & 1);
        float wt = ((cn >> 1) ? wy1 : wy0) * ((cn & 1) ? wx1 : wx0);
        bool valid = (yi >= 0) & (yi < HH) & (xi >= 0) & (xi < WW);
        float wv = valid ? wt : 0.f;
        int yc = min(max(yi, 0), HH - 1);
        int xc = min(max(xi, 0), WW - 1);
        uint4 v = xb[(yc * WW + xc) * 16 + tx];
        __half2 h0 = *reinterpret_cast<__half2*>(&v.x);
        __half2 h1 = *reinterpret_cast<__half2*>(&v.y);
        __half2 h2 = *reinterpret_cast<__half2*>(&v.z);
        __half2 h3 = *reinterpret_cast<__half2*>(&v.w);
        float2 f0 = __half22float2(h0);
        float2 f1 = __half22float2(h1);
        float2 f2 = __half22float2(h2);
        float2 f3 = __half22float2(h3);
        acc[0] += wv * f0.x; acc[1] += wv * f0.y;
        acc[2] += wv * f1.x; acc[3] += wv * f1.y;
        acc[4] += wv * f2.x; acc[5] += wv * f2.y;
        acc[6] += wv * f3.x; acc[7] += wv * f3.y;
    }
    #pragma unroll
    for (int i = 0; i < 8; i++) acc[i] *= m;

    __half2 p0 = __floats2half2_rn(acc[0], acc[1]);
    __half2 p1 = __floats2half2_rn(acc[2], acc[3]);
    __half2 p2 = __floats2half2_rn(acc[4], acc[5]);
    __half2 p3 = __floats2half2_rn(acc[6], acc[7]);
    uint4 u;
    u.x = *reinterpret_cast<uint32_t*>(&p0);
    u.y = *reinterpret_cast<uint32_t*>(&p1);
    u.z = *reinterpret_cast<uint32_t*>(&p2);
    u.w = *reinterpret_cast<uint32_t*>(&p3);

    size_t e = ((size_t)(b * HWSZ) + pos) * CK + kk * 128 + tx * 8;
    *reinterpret_cast<uint4*>((char*)g_V + e * 2) = u;
}

// ---------------- 4) fp16 GEMM, K-chunk 64, 18 iters, 2-stage -------------
#define ROWB       144                  // 128B data + 16B pad (bank-clean LDSM)
#define A_BYTES    (64 * ROWB)          // 9216
#define B_BYTES    (128 * ROWB)         // 18432
#define STAGE_B    (A_BYTES + B_BYTES)  // 27648
#define GEMM_SMEM  (2 * STAGE_B)        // 55296
#define ROWSKIP    ((size_t)64 * CK * 2)    // 64-row global stride in bytes

__global__ void __launch_bounds__(256, 4) k_gemm_f16() {
    extern __shared__ __align__(128) char sm[];
    const uint32_t base = smem_u32(sm);
    const int tid  = threadIdx.x;
    const int lane = tid & 31;
    const int wid  = tid >> 5;
    const int rowBlk = blockIdx.x * 64;
    const int colBlk = blockIdx.y * 128;

    const int warpRow = (wid & 1) * 32;     // 2 m-warps (m32 each)
    const int warpCol = (wid >> 1) * 32;    // 4 n-warps (n32 each)
    const int lrow  = lane & 15;
    const int lhalf = (lane >> 4) * 16;

    // ---- loader: fixed per-thread coords, pointers advance +128B/chunk
    const int ldrow = tid >> 2;             // 0..63
    const int ldcc  = (tid & 3) * 16;       // 0/16/32/48 (+64 second seg)
    const char* pa = (const char*)g_V
        + ((size_t)(rowBlk + ldrow) * CK) * 2 + ldcc;
    const char* pb = (const char*)g_Wh
        + ((size_t)(colBlk + ldrow) * CK) * 2 + ldcc;
    const uint32_t dA = (uint32_t)ldrow * ROWB + ldcc;
    const uint32_t dB = A_BYTES + (uint32_t)ldrow * ROWB + ldcc;

    float acc[2][4][4];
    #pragma unroll
    for (int mi = 0; mi < 2; mi++)
        #pragma unroll
        for (int ni = 0; ni < 4; ni++)
            #pragma unroll
            for (int q = 0; q < 4; q++) acc[mi][ni][q] = 0.f;

    // prologue: chunk 0 into stage 0
    {
        uint32_t buf = base;
        cp16(buf + dA,                      pa);
        cp16(buf + dA + 64,                 pa + 64);
        cp16(buf + dB,                      pb);
        cp16(buf + dB + 64,                 pb + 64);
        cp16(buf + dB + 64 * ROWB,          pb + ROWSKIP);
        cp16(buf + dB + 64 * ROWB + 64,     pb + ROWSKIP + 64);
        cp_commit();
        pa += 128; pb += 128;
    }

    int st = 0;
    for (int c = 0; c < 18; c++) {
        cp_wait<0>();
        __syncthreads();          // all warps done with the other buffer

        if (c + 1 < 18) {
            uint32_t buf = base + (st ^ 1) * STAGE_B;
            cp16(buf + dA,                  pa);
            cp16(buf + dA + 64,             pa + 64);
            cp16(buf + dB,                  pb);
            cp16(buf + dB + 64,             pb + 64);
            cp16(buf + dB + 64 * ROWB,      pb + ROWSKIP);
            cp16(buf + dB + 64 * ROWB + 64, pb + ROWSKIP + 64);
            cp_commit();
            pa += 128; pb += 128;
        }

        uint32_t bufA = base + st * STAGE_B;
        uint32_t bufB = bufA + A_BYTES;
        uint32_t arow0 = bufA + (uint32_t)(warpRow + lrow) * ROWB + lhalf;
        uint32_t brow0 = bufB + (uint32_t)(warpCol + lrow) * ROWB + lhalf;

        #pragma unroll
        for (int ks = 0; ks < 4; ks++) {
            uint32_t koff = ks * 32;
            uint32_t a0[4], a1[4], b0[4], b1[4];
            ldm_x4(a0, arow0 + koff);
            ldm_x4(a1, arow0 + 16 * ROWB + koff);
            ldm_x4(b0, brow0 + koff);
            ldm_x4(b1, brow0 + 16 * ROWB + koff);
            mma_f16(acc[0][0], a0, b0[0], b0[2]);
            mma_f16(acc[0][1], a0, b0[1], b0[3]);
            mma_f16(acc[0][2], a0, b1[0], b1[2]);
            mma_f16(acc[0][3], a0, b1[1], b1[3]);
            mma_f16(acc[1][0], a1, b0[0], b0[2]);
            mma_f16(acc[1][1], a1, b0[1], b0[3]);
            mma_f16(acc[1][2], a1, b1[0], b1[2]);
            mma_f16(acc[1][3], a1, b1[1], b1[3]);
        }

        st ^= 1;
    }
    __syncthreads();

    // ---- store C (warp m32 x n32)
    #pragma unroll
    for (int mi = 0; mi < 2; mi++) {
        int r0 = rowBlk + warpRow + mi * 16 + lane / 4;
        #pragma unroll
        for (int ni = 0; ni < 4; ni++) {
            int c0 = colBlk + warpCol + ni * 8 + (lane & 3) * 2;
            float2 v0 = make_float2(acc[mi][ni][0], acc[mi][ni][1]);
            float2 v1 = make_float2(acc[mi][ni][2], acc[mi][ni][3]);
            *(float2*)&g_outT[(size_t)r0 * COUT + c0]       = v0;
            *(float2*)&g_outT[(size_t)(r0 + 8) * COUT + c0] = v1;
        }
    }

    // ---- fused BN partials (deterministic)
    float* red_s  = (float*)sm;            // [8][32]
    float* red_ss = red_s + 8 * 32;        // [8][32]
    float sl[8], ssl[8];
    #pragma unroll
    for (int ni = 0; ni < 4; ni++) {
        #pragma unroll
        for (int j = 0; j < 2; j++) {
            float v0 = acc[0][ni][j], v1 = acc[0][ni][2 + j];
            float v2 = acc[1][ni][j], v3 = acc[1][ni][2 + j];
            sl [ni * 2 + j] = v0 + v1 + v2 + v3;
            ssl[ni * 2 + j] = v0 * v0 + v1 * v1 + v2 * v2 + v3 * v3;
        }
    }
    #pragma unroll
    for (int k = 0; k < 8; k++) {
        #pragma unroll
        for (int o = 4; o < 32; o <<= 1) {
            sl [k] += __shfl_down_sync(0xFFFFFFFFu, sl [k], o);
            ssl[k] += __shfl_down_sync(0xFFFFFFFFu, ssl[k], o);
        }
    }
    if (lane < 4) {
        #pragma unroll
        for (int ni = 0; ni < 4; ni++) {
            #pragma unroll
            for (int j = 0; j < 2; j++) {
                int cl = ni * 8 + lane * 2 + j;      // 0..31 within warp's n32
                red_s [wid * 32 + cl] = sl [ni * 2 + j];
                red_ss[wid * 32 + cl] = ssl[ni * 2 + j];
            }
        }
    }
    __syncthreads();
    if (tid < 128) {
        int col = tid;                 // 0..127 within colBlk
        int g   = col >> 5;            // which n-warp pair
        int cl  = col & 31;
        float s  = red_s [(2 * g) * 32 + cl] + red_s [(2 * g + 1) * 32 + cl];
        float ss = red_ss[(2 * g) * 32 + cl] + red_ss[(2 * g + 1) * 32 + cl];
        int ch = colBlk + col;
        g_part[blockIdx.x * 512 + ch]       = s;
        g_part[blockIdx.x * 512 + 256 + ch] = ss;
    }
}

// ---------------- 5) finalize BN scale/shift -----------------------------
__global__ void k_bn_final(const float* __restrict__ gamma,
                           const float* __restrict__ beta) {
    int t = threadIdx.x;
    float s = 0.f, ss = 0.f;
    for (int i = 0; i < 512; i++) {
        s  += g_part[i * 512 + t];
        ss += g_part[i * 512 + 256 + t];
    }
    const float invN = 1.f / 32768.f;
    float mean = s * invN;
    float var  = ss * invN - mean * mean;
    float inv  = rsqrtf(var + 1e-5f);
    float sc   = gamma[t] * inv;
    g_scale[t] = sc;
    g_shift[t] = beta[t] - mean * sc;
}

// ---------------- 6) affine + SiLU + transpose to NCHW -------------------
__global__ void k_epilogue(float* __restrict__ out) {
    __shared__ float tile[32][33];
    int tx = threadIdx.x, ty = threadIdx.y;
    int o0 = blockIdx.y * 32;
    int r0 = blockIdx.x * 32;
    int orq = o0 + tx;
    float sc = g_scale[orq], sh = g_shift[orq];
    #pragma unroll
    for (int j = 0; j < 4; j++) {
        int r = r0 + ty + j * 8;
        float v = g_outT[(size_t)r * COUT + orq] * sc + sh;
        v = v / (1.f + __expf(-v));
        tile[ty + j * 8][tx] = v;
    }
    __syncthreads();
    int rw = r0 + tx;
    int bb = rw >> 12;
    int hw = rw & 4095;
    #pragma unroll
    for (int j = 0; j < 4; j++) {
        int o = o0 + ty + j * 8;
        out[((size_t)(bb * COUT + o)) * HWSZ + hw] = tile[tx][ty + j * 8];
    }
}

// ---------------- launch ---------------------------------------------------
extern "C" void kernel_launch(void* const* d_in, const int* in_sizes, int n_in,
                              void* d_out, int out_size) {
    const float* x     = (const float*)d_in[0];
    const float* w_off = (const float*)d_in[1];
    const float* b_off = (const float*)d_in[2];
    const float* w_mod = (const float*)d_in[3];
    const float* b_mod = (const float*)d_in[4];
    const float* w_dc  = (const float*)d_in[5];
    const float* gamma = (const float*)d_in[6];
    const float* beta  = (const float*)d_in[7];
    float* out = (float*)d_out;

    cudaFuncSetAttribute(k_conv_tc,  cudaFuncAttributeMaxDynamicSharedMemorySize, CONV_SMEM);
    cudaFuncSetAttribute(k_gemm_f16, cudaFuncAttributeMaxDynamicSharedMemorySize, GEMM_SMEM);

    k_prep<<<dim3(HWSZ / 32, CIN / 32, 9), dim3(32, 8)>>>(x, w_dc, w_off, w_mod);

    k_conv_tc<<<256, 256, CONV_SMEM>>>(b_off, b_mod);

    k_sample<<<dim3(HWSZ / 16, KK9, BATCH), dim3(16, 16)>>>();

    k_gemm_f16<<<dim3(ROWS / 64, 2), 256, GEMM_SMEM>>>();

    k_bn_final<<<1, 256>>>(gamma, beta);

    k_epilogue<<<dim3((BATCH * HWSZ) / 32, COUT / 32), dim3(32, 8)>>>(out);
}

// round 14
// speedup vs baseline: 1.1651x; 1.1651x over previous
#include <cuda_runtime.h>
#include <cuda_fp16.h>
#include <stdint.h>
#include <math.h>

// ---------------- problem constants ----------------
#define BATCH 8
#define CIN   128
#define COUT  256
#define HH    64
#define WW    64
#define HWSZ  4096
#define KK9   9
#define CK    1152          // CIN*KK9
#define NOC   27            // 18 offset + 9 modulation channels
#define ROWS  (BATCH*HWSZ)  // 32768

// ---------------- scratch ------------------------------------------------
__device__ __half g_xTh[BATCH * HWSZ * CIN];        // x channels-last fp16
__device__ float  g_off[BATCH * NOC * HWSZ];        // offsets + modulation(sigmoid)
__device__ __half g_Wch[32 * CK];                   // conv weights fp16, padded to 32 oc
__device__ __half g_Wh [COUT * CK];                 // deform weights fp16
__device__ __half g_V  [(size_t)ROWS * CK];         // sampled*mod fp16
__device__ float  g_outT[(size_t)ROWS * COUT];
__device__ float  g_part [512 * 512];
__device__ float  g_part2[32 * 512];
__device__ float  g_scale[COUT];
__device__ float  g_shift[COUT];

// ---------------- ptx helpers (plain sm_80+ PTX only) --------------------
__device__ __forceinline__ uint32_t smem_u32(const void* p) {
    uint32_t a;
    asm("{ .reg .u64 t; cvta.to.shared.u64 t, %1; cvt.u32.u64 %0, t; }"
        : "=r"(a) : "l"(p));
    return a;
}
__device__ __forceinline__ void cp16(uint32_t dst, const void* src) {
    asm volatile("cp.async.cg.shared.global [%0], [%1], 16;" :: "r"(dst), "l"(src));
}
__device__ __forceinline__ void cp16z(uint32_t dst, const void* src, uint32_t sz) {
    asm volatile("cp.async.cg.shared.global [%0], [%1], 16, %2;"
                 :: "r"(dst), "l"(src), "r"(sz));
}
__device__ __forceinline__ void cp_commit() {
    asm volatile("cp.async.commit_group;" ::: "memory");
}
template <int N>
__device__ __forceinline__ void cp_wait() {
    asm volatile("cp.async.wait_group %0;" :: "n"(N) : "memory");
}
__device__ __forceinline__ void ldm_x4(uint32_t* r, uint32_t addr) {
    asm volatile("ldmatrix.sync.aligned.m8n8.x4.shared.b16 {%0,%1,%2,%3}, [%4];"
        : "=r"(r[0]), "=r"(r[1]), "=r"(r[2]), "=r"(r[3]) : "r"(addr));
}
__device__ __forceinline__ void mma_f16(float* d, const uint32_t* a,
                                        uint32_t b0, uint32_t b1) {
    asm volatile(
        "mma.sync.aligned.m16n8k16.row.col.f32.f16.f16.f32 "
        "{%0,%1,%2,%3}, {%4,%5,%6,%7}, {%8,%9}, {%0,%1,%2,%3};"
        : "+f"(d[0]), "+f"(d[1]), "+f"(d[2]), "+f"(d[3])
        : "r"(a[0]), "r"(a[1]), "r"(a[2]), "r"(a[3]), "r"(b0), "r"(b1));
}

// ---------------- 1) prep: transpose x -> fp16 channels-last + weights ---
__global__ void k_prep(const float* __restrict__ x,
                       const float* __restrict__ w_dc,
                       const float* __restrict__ w_off,
                       const float* __restrict__ w_mod) {
    if (blockIdx.z < 8) {
        __shared__ float tile[32][33];
        int b   = blockIdx.z;
        int hw0 = blockIdx.x * 32;
        int c0  = blockIdx.y * 32;
        int tx = threadIdx.x, ty = threadIdx.y;
        #pragma unroll
        for (int j = 0; j < 4; j++) {
            int c = c0 + ty + j * 8;
            tile[ty + j * 8][tx] = x[((b * CIN) + c) * HWSZ + hw0 + tx];
        }
        __syncthreads();
        #pragma unroll
        for (int j = 0; j < 4; j++) {
            int hw = hw0 + ty + j * 8;
            size_t o = ((size_t)(b * HWSZ) + hw) * CIN + c0 + tx;
            g_xTh[o] = __float2half(tile[tx][ty + j * 8]);
        }
    } else {
        const int NWP  = COUT * CK;         // 294912
        const int NWC2 = 32 * CK;           // 36864
        int t = threadIdx.y * 32 + threadIdx.x;
        int gidx = (blockIdx.y * 128 + blockIdx.x) * 256 + t;
        for (int idx = gidx; idx < NWP + NWC2; idx += 512 * 256) {
            if (idx < NWP) {
                int o  = idx / CK;
                int r  = idx - o * CK;
                int kk = r >> 7;
                int c  = r & 127;
                g_Wh[idx] = __float2half(w_dc[(o * CIN + c) * KK9 + kk]);
            } else {
                int j  = idx - NWP;
                int oc = j / CK;
                int r  = j - oc * CK;
                int kk = r >> 7;
                int c  = r & 127;
                float v = 0.f;
                if (oc < 18)      v = w_off[(oc * CIN + c) * KK9 + kk];
                else if (oc < 27) v = w_mod[((oc - 18) * CIN + c) * KK9 + kk];
                g_Wch[j] = __float2half(v);
            }
        }
    }
}

// ---------------- 2) conv offsets/mod via tensor cores (64-px tiles) -----
#define RCWB   80
#define A2_B   (64 * RCWB)                  // 5120
#define B2_B   (32 * RCWB)                  // 2560
#define CSTG   (A2_B + B2_B)                // 7680
#define CONV_SMEM (2 * CSTG)                // 15360

__device__ __forceinline__ void conv_load_stage(uint32_t buf, int cn,
                                                int rowBlk, int tid) {
    int kk  = cn >> 2;
    int c0k = (cn & 3) * 32;
    int dy = kk / 3 - 1;
    int dx = kk % 3 - 1;
    // A: 64 rows x 64B (256 cp16)
    {
        int row = tid >> 2;
        int cc  = tid & 3;
        int pix = rowBlk * 64 + row;
        int b = pix >> 12;
        int h = (pix >> 6) & 63;
        int w = pix & 63;
        int h2 = h + dy, w2 = w + dx;
        bool valid = ((unsigned)h2 < 64u) & ((unsigned)w2 < 64u);
        size_t srcoff = valid
            ? (((size_t)b * HWSZ + h2 * 64 + w2) * CIN + c0k) * 2 : 0;
        uint32_t sz = valid ? 16u : 0u;
        cp16z(buf + row * RCWB + cc * 16, (const char*)g_xTh + srcoff + cc * 16, sz);
    }
    // B: 32 rows x 64B (128 cp16)
    if (tid < 128) {
        int row = tid >> 2;
        int q   = tid & 3;
        const char* src = (const char*)g_Wch + ((size_t)row * CK + cn * 32) * 2 + q * 16;
        cp16(buf + A2_B + row * RCWB + q * 16, src);
    }
}

__global__ void __launch_bounds__(256) k_conv_tc(const float* __restrict__ b_off,
                                                 const float* __restrict__ b_mod) {
    extern __shared__ __align__(128) char sm[];
    const uint32_t base = smem_u32(sm);
    const int tid  = threadIdx.x;
    const int lane = tid & 31;
    const int wid  = tid >> 5;
    const int rowBlk = blockIdx.x;           // 512 tiles of 64 pixels

    const int warpRow = (wid & 3) * 16;      // 4 m-warps (m16)
    const int warpCol = (wid >> 2) * 16;     // 2 n-halves (n16)
    const int lrow  = lane & 15;
    const int lhalf = (lane >> 4) * 16;

    float acc[2][4];
    #pragma unroll
    for (int i = 0; i < 2; i++)
        #pragma unroll
        for (int q = 0; q < 4; q++) acc[i][q] = 0.f;

    conv_load_stage(base, 0, rowBlk, tid);
    cp_commit();

    for (int cn = 0; cn < 36; cn++) {
        int s = cn & 1;
        if (cn + 1 < 36) {
            conv_load_stage(base + ((cn + 1) & 1) * CSTG, cn + 1, rowBlk, tid);
            cp_commit();
            cp_wait<1>();
        } else {
            cp_wait<0>();
        }
        __syncthreads();

        uint32_t bufA = base + s * CSTG;
        uint32_t bufB = bufA + A2_B;

        #pragma unroll
        for (int ks = 0; ks < 2; ks++) {
            uint32_t a[4], bfr[4];
            ldm_x4(a,   bufA + (uint32_t)(warpRow + lrow) * RCWB + ks * 32 + lhalf);
            ldm_x4(bfr, bufB + (uint32_t)(warpCol + lrow) * RCWB + ks * 32 + lhalf);
            mma_f16(acc[0], a, bfr[0], bfr[2]);
            mma_f16(acc[1], a, bfr[1], bfr[3]);
        }
        __syncthreads();
    }

    int pix0 = rowBlk * 64 + warpRow + (lane >> 2);
    int b = pix0 >> 12;
    #pragma unroll
    for (int ni = 0; ni < 2; ni++) {
        #pragma unroll
        for (int q = 0; q < 4; q++) {
            int oc = warpCol + ni * 8 + (lane & 3) * 2 + (q & 1);
            if (oc >= NOC) continue;
            int pix = pix0 + (q >> 1) * 8;
            float bias = (oc < 18) ? b_off[oc] : b_mod[oc - 18];
            float v = acc[ni][q] + bias;
            if (oc >= 18) v = 1.f / (1.f + __expf(-v));
            g_off[((size_t)b * NOC + oc) * HWSZ + (pix & 4095)] = v;
        }
    }
}

// ---------------- 3) bilinear sampling (fp16 src, 8 ch/thread) -----------
__global__ void __launch_bounds__(256) k_sample() {
    int tx  = threadIdx.x;                  // 0..15 channel octet
    int pos = blockIdx.x * 16 + threadIdx.y;
    int kk  = blockIdx.y;
    int b   = blockIdx.z;
    int h = pos >> 6, w = pos & 63;

    const float* offb = g_off + (b * NOC) * HWSZ;
    float dy = offb[(2 * kk)     * HWSZ + pos];
    float dx = offb[(2 * kk + 1) * HWSZ + pos];
    float m  = offb[(18 + kk)    * HWSZ + pos];

    float py = dy + (float)(h - 1 + kk / 3);
    float px = dx + (float)(w - 1 + kk % 3);
    float fy = floorf(py), fx = floorf(px);
    int y0 = (int)fy, x0 = (int)fx;
    float wy1 = py - fy, wx1 = px - fx;
    float wy0 = 1.f - wy1, wx0 = 1.f - wx1;

    const uint4* xb = (const uint4*)g_xTh + (size_t)(b * HWSZ) * 16;
    float acc[8];
    #pragma unroll
    for (int i = 0; i < 8; i++) acc[i] = 0.f;

    #pragma unroll
    for (int cn = 0; cn < 4; cn++) {
        int yi = y0 + (cn >> 1);
        int xi = x0 + (cn & 1);
        float wt = ((cn >> 1) ? wy1 : wy0) * ((cn & 1) ? wx1 : wx0);
        bool valid = (yi >= 0) & (yi < HH) & (xi >= 0) & (xi < WW);
        float wv = valid ? wt : 0.f;
        int yc = min(max(yi, 0), HH - 1);
        int xc = min(max(xi, 0), WW - 1);
        uint4 v = xb[(yc * WW + xc) * 16 + tx];
        __half2 h0 = *reinterpret_cast<__half2*>(&v.x);
        __half2 h1 = *reinterpret_cast<__half2*>(&v.y);
        __half2 h2 = *reinterpret_cast<__half2*>(&v.z);
        __half2 h3 = *reinterpret_cast<__half2*>(&v.w);
        float2 f0 = __half22float2(h0);
        float2 f1 = __half22float2(h1);
        float2 f2 = __half22float2(h2);
        float2 f3 = __half22float2(h3);
        acc[0] += wv * f0.x; acc[1] += wv * f0.y;
        acc[2] += wv * f1.x; acc[3] += wv * f1.y;
        acc[4] += wv * f2.x; acc[5] += wv * f2.y;
        acc[6] += wv * f3.x; acc[7] += wv * f3.y;
    }
    #pragma unroll
    for (int i = 0; i < 8; i++) acc[i] *= m;

    __half2 p0 = __floats2half2_rn(acc[0], acc[1]);
    __half2 p1 = __floats2half2_rn(acc[2], acc[3]);
    __half2 p2 = __floats2half2_rn(acc[4], acc[5]);
    __half2 p3 = __floats2half2_rn(acc[6], acc[7]);
    uint4 u;
    u.x = *reinterpret_cast<uint32_t*>(&p0);
    u.y = *reinterpret_cast<uint32_t*>(&p1);
    u.z = *reinterpret_cast<uint32_t*>(&p2);
    u.w = *reinterpret_cast<uint32_t*>(&p3);

    size_t e = ((size_t)(b * HWSZ) + pos) * CK + kk * 128 + tx * 8;
    *reinterpret_cast<uint4*>((char*)g_V + e * 2) = u;
}

// ---------------- 4) fp16 GEMM (R12 config: m32n32, 3-stage, prefetch) ----
#define ROWB       80
#define A_BYTES    (64 * ROWB)         // 5120
#define B_BYTES    (128 * ROWB)        // 10240
#define STAGE_B    (A_BYTES + B_BYTES) // 15360
#define NSTG       3
#define GEMM_SMEM  (NSTG * STAGE_B)    // 46080
#define ROWSKIP    ((size_t)64 * CK * 2)   // 64-row global stride in bytes

__global__ void __launch_bounds__(256, 4) k_gemm_f16() {
    extern __shared__ __align__(128) char sm[];
    const uint32_t base = smem_u32(sm);
    const int tid  = threadIdx.x;
    const int lane = tid & 31;
    const int wid  = tid >> 5;
    const int rowBlk = blockIdx.x * 64;
    const int colBlk = blockIdx.y * 128;

    const int warpRow = (wid & 1) * 32;     // 2 m-warps (m32 each)
    const int warpCol = (wid >> 1) * 32;    // 4 n-warps (n32 each)
    const int lrow  = lane & 15;
    const int lhalf = (lane >> 4) * 16;

    const int ldrow = tid >> 2;             // 0..63
    const int ldcc  = (tid & 3) * 16;       // 0/16/32/48
    const char* pa = (const char*)g_V
        + ((size_t)(rowBlk + ldrow) * CK) * 2 + ldcc;
    const char* pb = (const char*)g_Wh
        + ((size_t)(colBlk + ldrow) * CK) * 2 + ldcc;
    const uint32_t dA = (uint32_t)ldrow * ROWB + ldcc;
    const uint32_t dB = A_BYTES + (uint32_t)ldrow * ROWB + ldcc;

    float acc[2][4][4];
    #pragma unroll
    for (int mi = 0; mi < 2; mi++)
        #pragma unroll
        for (int ni = 0; ni < 4; ni++)
            #pragma unroll
            for (int q = 0; q < 4; q++) acc[mi][ni][q] = 0.f;

    #pragma unroll
    for (int p = 0; p < 2; p++) {
        uint32_t buf = base + p * STAGE_B;
        cp16(buf + dA,                 pa);
        cp16(buf + dB,                 pb);
        cp16(buf + dB + 64 * ROWB,     pb + ROWSKIP);
        cp_commit();
        pa += 64; pb += 64;
    }

    int st = 0;
    for (int c = 0; c < 36; c++) {
        if (c + 1 < 36) cp_wait<1>(); else cp_wait<0>();
        __syncthreads();

        if (c + 2 < 36) {
            int nst = st + 2; if (nst >= NSTG) nst -= NSTG;
            uint32_t buf = base + nst * STAGE_B;
            cp16(buf + dA,             pa);
            cp16(buf + dB,             pb);
            cp16(buf + dB + 64 * ROWB, pb + ROWSKIP);
            cp_commit();
            pa += 64; pb += 64;
        }

        uint32_t bufA = base + st * STAGE_B;
        uint32_t bufB = bufA + A_BYTES;
        uint32_t arow0 = bufA + (uint32_t)(warpRow + lrow) * ROWB + lhalf;
        uint32_t brow0 = bufB + (uint32_t)(warpCol + lrow) * ROWB + lhalf;

        uint32_t a00[4], a01[4], a10[4], a11[4], b0[4], b1[4];
        ldm_x4(a00, arow0);
        ldm_x4(a01, arow0 + 16 * ROWB);
        ldm_x4(b0,  brow0);
        ldm_x4(b1,  brow0 + 16 * ROWB);
        ldm_x4(a10, arow0 + 32);
        ldm_x4(a11, arow0 + 16 * ROWB + 32);

        mma_f16(acc[0][0], a00, b0[0], b0[2]);
        mma_f16(acc[0][1], a00, b0[1], b0[3]);
        mma_f16(acc[0][2], a00, b1[0], b1[2]);
        mma_f16(acc[0][3], a00, b1[1], b1[3]);
        mma_f16(acc[1][0], a01, b0[0], b0[2]);
        mma_f16(acc[1][1], a01, b0[1], b0[3]);
        mma_f16(acc[1][2], a01, b1[0], b1[2]);
        mma_f16(acc[1][3], a01, b1[1], b1[3]);

        ldm_x4(b0, brow0 + 32);
        ldm_x4(b1, brow0 + 16 * ROWB + 32);
        mma_f16(acc[0][0], a10, b0[0], b0[2]);
        mma_f16(acc[0][1], a10, b0[1], b0[3]);
        mma_f16(acc[0][2], a10, b1[0], b1[2]);
        mma_f16(acc[0][3], a10, b1[1], b1[3]);
        mma_f16(acc[1][0], a11, b0[0], b0[2]);
        mma_f16(acc[1][1], a11, b0[1], b0[3]);
        mma_f16(acc[1][2], a11, b1[0], b1[2]);
        mma_f16(acc[1][3], a11, b1[1], b1[3]);

        st++; if (st >= NSTG) st = 0;
    }
    __syncthreads();

    #pragma unroll
    for (int mi = 0; mi < 2; mi++) {
        int r0 = rowBlk + warpRow + mi * 16 + lane / 4;
        #pragma unroll
        for (int ni = 0; ni < 4; ni++) {
            int c0 = colBlk + warpCol + ni * 8 + (lane & 3) * 2;
            float2 v0 = make_float2(acc[mi][ni][0], acc[mi][ni][1]);
            float2 v1 = make_float2(acc[mi][ni][2], acc[mi][ni][3]);
            *(float2*)&g_outT[(size_t)r0 * COUT + c0]       = v0;
            *(float2*)&g_outT[(size_t)(r0 + 8) * COUT + c0] = v1;
        }
    }

    // ---- fused BN partials (deterministic)
    float* red_s  = (float*)sm;            // [8][32]
    float* red_ss = red_s + 8 * 32;        // [8][32]
    float sl[8], ssl[8];
    #pragma unroll
    for (int ni = 0; ni < 4; ni++) {
        #pragma unroll
        for (int j = 0; j < 2; j++) {
            float v0 = acc[0][ni][j], v1 = acc[0][ni][2 + j];
            float v2 = acc[1][ni][j], v3 = acc[1][ni][2 + j];
            sl [ni * 2 + j] = v0 + v1 + v2 + v3;
            ssl[ni * 2 + j] = v0 * v0 + v1 * v1 + v2 * v2 + v3 * v3;
        }
    }
    #pragma unroll
    for (int k = 0; k < 8; k++) {
        #pragma unroll
        for (int o = 4; o < 32; o <<= 1) {
            sl [k] += __shfl_down_sync(0xFFFFFFFFu, sl [k], o);
            ssl[k] += __shfl_down_sync(0xFFFFFFFFu, ssl[k], o);
        }
    }
    if (lane < 4) {
        #pragma unroll
        for (int ni = 0; ni < 4; ni++) {
            #pragma unroll
            for (int j = 0; j < 2; j++) {
                int cl = ni * 8 + lane * 2 + j;
                red_s [wid * 32 + cl] = sl [ni * 2 + j];
                red_ss[wid * 32 + cl] = ssl[ni * 2 + j];
            }
        }
    }
    __syncthreads();
    if (tid < 128) {
        int col = tid;
        int g   = col >> 5;
        int cl  = col & 31;
        float s  = red_s [(2 * g) * 32 + cl] + red_s [(2 * g + 1) * 32 + cl];
        float ss = red_ss[(2 * g) * 32 + cl] + red_ss[(2 * g + 1) * 32 + cl];
        int ch = colBlk + col;
        g_part[blockIdx.x * 512 + ch]       = s;
        g_part[blockIdx.x * 512 + 256 + ch] = ss;
    }
}

// ---------------- 5) BN reduction level 1 (32 blocks) ---------------------
__global__ void k_bn_lvl1() {
    int blk = blockIdx.x;          // 0..31, each sums 16 row-tiles
    int t = threadIdx.x;           // 0..255
    float s = 0.f, ss = 0.f;
    #pragma unroll
    for (int i = 0; i < 16; i++) {
        int r = blk * 16 + i;
        s  += g_part[r * 512 + t];
        ss += g_part[r * 512 + 256 + t];
    }
    g_part2[blk * 512 + t]       = s;
    g_part2[blk * 512 + 256 + t] = ss;
}

// ---------------- 6) finalize BN scale/shift -----------------------------
__global__ void k_bn_final(const float* __restrict__ gamma,
                           const float* __restrict__ beta) {
    int t = threadIdx.x;
    float s = 0.f, ss = 0.f;
    #pragma unroll
    for (int i = 0; i < 32; i++) {
        s  += g_part2[i * 512 + t];
        ss += g_part2[i * 512 + 256 + t];
    }
    const float invN = 1.f / 32768.f;
    float mean = s * invN;
    float var  = ss * invN - mean * mean;
    float inv  = rsqrtf(var + 1e-5f);
    float sc   = gamma[t] * inv;
    g_scale[t] = sc;
    g_shift[t] = beta[t] - mean * sc;
}

// ---------------- 7) affine + SiLU + transpose to NCHW -------------------
__global__ void k_epilogue(float* __restrict__ out) {
    __shared__ float tile[32][33];
    int tx = threadIdx.x, ty = threadIdx.y;
    int o0 = blockIdx.y * 32;
    int r0 = blockIdx.x * 32;
    int orq = o0 + tx;
    float sc = g_scale[orq], sh = g_shift[orq];
    #pragma unroll
    for (int j = 0; j < 4; j++) {
        int r = r0 + ty + j * 8;
        float v = g_outT[(size_t)r * COUT + orq] * sc + sh;
        v = v / (1.f + __expf(-v));
        tile[ty + j * 8][tx] = v;
    }
    __syncthreads();
    int rw = r0 + tx;
    int bb = rw >> 12;
    int hw = rw & 4095;
    #pragma unroll
    for (int j = 0; j < 4; j++) {
        int o = o0 + ty + j * 8;
        out[((size_t)(bb * COUT + o)) * HWSZ + hw] = tile[tx][ty + j * 8];
    }
}

// ---------------- launch ---------------------------------------------------
extern "C" void kernel_launch(void* const* d_in, const int* in_sizes, int n_in,
                              void* d_out, int out_size) {
    const float* x     = (const float*)d_in[0];
    const float* w_off = (const float*)d_in[1];
    const float* b_off = (const float*)d_in[2];
    const float* w_mod = (const float*)d_in[3];
    const float* b_mod = (const float*)d_in[4];
    const float* w_dc  = (const float*)d_in[5];
    const float* gamma = (const float*)d_in[6];
    const float* beta  = (const float*)d_in[7];
    float* out = (float*)d_out;

    cudaFuncSetAttribute(k_conv_tc,  cudaFuncAttributeMaxDynamicSharedMemorySize, CONV_SMEM);
    cudaFuncSetAttribute(k_gemm_f16, cudaFuncAttributeMaxDynamicSharedMemorySize, GEMM_SMEM);

    k_prep<<<dim3(HWSZ / 32, CIN / 32, 9), dim3(32, 8)>>>(x, w_dc, w_off, w_mod);

    k_conv_tc<<<512, 256, CONV_SMEM>>>(b_off, b_mod);

    k_sample<<<dim3(HWSZ / 16, KK9, BATCH), dim3(16, 16)>>>();

    k_gemm_f16<<<dim3(ROWS / 64, 2), 256, GEMM_SMEM>>>();

    k_bn_lvl1<<<32, 256>>>();
    k_bn_final<<<1, 256>>>(gamma, beta);

    k_epilogue<<<dim3((BATCH * HWSZ) / 32, COUT / 32), dim3(32, 8)>>>(out);
}

// round 15
// speedup vs baseline: 1.1833x; 1.0156x over previous
#include <cuda_runtime.h>
#include <cuda_fp16.h>
#include <stdint.h>
#include <math.h>

// ---------------- problem constants ----------------
#define BATCH 8
#define CIN   128
#define COUT  256
#define HH    64
#define WW    64
#define HWSZ  4096
#define KK9   9
#define CK    1152          // CIN*KK9
#define NOC   27            // 18 offset + 9 modulation channels
#define ROWS  (BATCH*HWSZ)  // 32768

// ---------------- scratch ------------------------------------------------
__device__ __half g_xTh[BATCH * HWSZ * CIN];        // x channels-last fp16
__device__ float  g_off[BATCH * NOC * HWSZ];        // offsets + modulation(sigmoid)
__device__ __half g_Wch[32 * CK];                   // conv weights fp16, padded to 32 oc
__device__ __half g_Wh [COUT * CK];                 // deform weights fp16
__device__ __half g_V  [(size_t)ROWS * CK];         // sampled*mod fp16
__device__ __half g_outTh[(size_t)ROWS * COUT];     // GEMM result (fp16)
__device__ float  g_part [512 * 512];
__device__ float  g_part2[32 * 512];
__device__ float  g_scale[COUT];
__device__ float  g_shift[COUT];

// ---------------- ptx helpers (plain sm_80+ PTX only) --------------------
__device__ __forceinline__ uint32_t smem_u32(const void* p) {
    uint32_t a;
    asm("{ .reg .u64 t; cvta.to.shared.u64 t, %1; cvt.u32.u64 %0, t; }"
        : "=r"(a) : "l"(p));
    return a;
}
__device__ __forceinline__ void cp16(uint32_t dst, const void* src) {
    asm volatile("cp.async.cg.shared.global [%0], [%1], 16;" :: "r"(dst), "l"(src));
}
__device__ __forceinline__ void cp16z(uint32_t dst, const void* src, uint32_t sz) {
    asm volatile("cp.async.cg.shared.global [%0], [%1], 16, %2;"
                 :: "r"(dst), "l"(src), "r"(sz));
}
__device__ __forceinline__ void cp_commit() {
    asm volatile("cp.async.commit_group;" ::: "memory");
}
template <int N>
__device__ __forceinline__ void cp_wait() {
    asm volatile("cp.async.wait_group %0;" :: "n"(N) : "memory");
}
__device__ __forceinline__ void ldm_x4(uint32_t* r, uint32_t addr) {
    asm volatile("ldmatrix.sync.aligned.m8n8.x4.shared.b16 {%0,%1,%2,%3}, [%4];"
        : "=r"(r[0]), "=r"(r[1]), "=r"(r[2]), "=r"(r[3]) : "r"(addr));
}
__device__ __forceinline__ void mma_f16(float* d, const uint32_t* a,
                                        uint32_t b0, uint32_t b1) {
    asm volatile(
        "mma.sync.aligned.m16n8k16.row.col.f32.f16.f16.f32 "
        "{%0,%1,%2,%3}, {%4,%5,%6,%7}, {%8,%9}, {%0,%1,%2,%3};"
        : "+f"(d[0]), "+f"(d[1]), "+f"(d[2]), "+f"(d[3])
        : "r"(a[0]), "r"(a[1]), "r"(a[2]), "r"(a[3]), "r"(b0), "r"(b1));
}

// ---------------- 1) prep: transpose x -> fp16 channels-last + weights ---
__global__ void k_prep(const float* __restrict__ x,
                       const float* __restrict__ w_dc,
                       const float* __restrict__ w_off,
                       const float* __restrict__ w_mod) {
    if (blockIdx.z < 8) {
        __shared__ float tile[32][33];
        int b   = blockIdx.z;
        int hw0 = blockIdx.x * 32;
        int c0  = blockIdx.y * 32;
        int tx = threadIdx.x, ty = threadIdx.y;
        #pragma unroll
        for (int j = 0; j < 4; j++) {
            int c = c0 + ty + j * 8;
            tile[ty + j * 8][tx] = x[((b * CIN) + c) * HWSZ + hw0 + tx];
        }
        __syncthreads();
        #pragma unroll
        for (int j = 0; j < 4; j++) {
            int hw = hw0 + ty + j * 8;
            size_t o = ((size_t)(b * HWSZ) + hw) * CIN + c0 + tx;
            g_xTh[o] = __float2half(tile[tx][ty + j * 8]);
        }
    } else {
        const int NWP  = COUT * CK;         // 294912
        const int NWC2 = 32 * CK;           // 36864
        int t = threadIdx.y * 32 + threadIdx.x;
        int gidx = (blockIdx.y * 128 + blockIdx.x) * 256 + t;
        for (int idx = gidx; idx < NWP + NWC2; idx += 512 * 256) {
            if (idx < NWP) {
                int o  = idx / CK;
                int r  = idx - o * CK;
                int kk = r >> 7;
                int c  = r & 127;
                g_Wh[idx] = __float2half(w_dc[(o * CIN + c) * KK9 + kk]);
            } else {
                int j  = idx - NWP;
                int oc = j / CK;
                int r  = j - oc * CK;
                int kk = r >> 7;
                int c  = r & 127;
                float v = 0.f;
                if (oc < 18)      v = w_off[(oc * CIN + c) * KK9 + kk];
                else if (oc < 27) v = w_mod[((oc - 18) * CIN + c) * KK9 + kk];
                g_Wch[j] = __float2half(v);
            }
        }
    }
}

// ---------------- 2) conv offsets/mod via tensor cores (64-px tiles) -----
#define RCWB   80
#define A2_B   (64 * RCWB)                  // 5120
#define B2_B   (32 * RCWB)                  // 2560
#define CSTG   (A2_B + B2_B)                // 7680
#define CONV_SMEM (2 * CSTG)                // 15360

__device__ __forceinline__ void conv_load_stage(uint32_t buf, int cn,
                                                int rowBlk, int tid) {
    int kk  = cn >> 2;
    int c0k = (cn & 3) * 32;
    int dy = kk / 3 - 1;
    int dx = kk % 3 - 1;
    // A: 64 rows x 64B (256 cp16)
    {
        int row = tid >> 2;
        int cc  = tid & 3;
        int pix = rowBlk * 64 + row;
        int b = pix >> 12;
        int h = (pix >> 6) & 63;
        int w = pix & 63;
        int h2 = h + dy, w2 = w + dx;
        bool valid = ((unsigned)h2 < 64u) & ((unsigned)w2 < 64u);
        size_t srcoff = valid
            ? (((size_t)b * HWSZ + h2 * 64 + w2) * CIN + c0k) * 2 : 0;
        uint32_t sz = valid ? 16u : 0u;
        cp16z(buf + row * RCWB + cc * 16, (const char*)g_xTh + srcoff + cc * 16, sz);
    }
    // B: 32 rows x 64B (128 cp16)
    if (tid < 128) {
        int row = tid >> 2;
        int q   = tid & 3;
        const char* src = (const char*)g_Wch + ((size_t)row * CK + cn * 32) * 2 + q * 16;
        cp16(buf + A2_B + row * RCWB + q * 16, src);
    }
}

__global__ void __launch_bounds__(256) k_conv_tc(const float* __restrict__ b_off,
                                                 const float* __restrict__ b_mod) {
    extern __shared__ __align__(128) char sm[];
    const uint32_t base = smem_u32(sm);
    const int tid  = threadIdx.x;
    const int lane = tid & 31;
    const int wid  = tid >> 5;
    const int rowBlk = blockIdx.x;           // 512 tiles of 64 pixels

    const int warpRow = (wid & 3) * 16;      // 4 m-warps (m16)
    const int warpCol = (wid >> 2) * 16;     // 2 n-halves (n16)
    const int lrow  = lane & 15;
    const int lhalf = (lane >> 4) * 16;

    float acc[2][4];
    #pragma unroll
    for (int i = 0; i < 2; i++)
        #pragma unroll
        for (int q = 0; q < 4; q++) acc[i][q] = 0.f;

    conv_load_stage(base, 0, rowBlk, tid);
    cp_commit();

    for (int cn = 0; cn < 36; cn++) {
        int s = cn & 1;
        if (cn + 1 < 36) {
            conv_load_stage(base + ((cn + 1) & 1) * CSTG, cn + 1, rowBlk, tid);
            cp_commit();
            cp_wait<1>();
        } else {
            cp_wait<0>();
        }
        __syncthreads();

        uint32_t bufA = base + s * CSTG;
        uint32_t bufB = bufA + A2_B;

        #pragma unroll
        for (int ks = 0; ks < 2; ks++) {
            uint32_t a[4], bfr[4];
            ldm_x4(a,   bufA + (uint32_t)(warpRow + lrow) * RCWB + ks * 32 + lhalf);
            ldm_x4(bfr, bufB + (uint32_t)(warpCol + lrow) * RCWB + ks * 32 + lhalf);
            mma_f16(acc[0], a, bfr[0], bfr[2]);
            mma_f16(acc[1], a, bfr[1], bfr[3]);
        }
        __syncthreads();
    }

    int pix0 = rowBlk * 64 + warpRow + (lane >> 2);
    int b = pix0 >> 12;
    #pragma unroll
    for (int ni = 0; ni < 2; ni++) {
        #pragma unroll
        for (int q = 0; q < 4; q++) {
            int oc = warpCol + ni * 8 + (lane & 3) * 2 + (q & 1);
            if (oc >= NOC) continue;
            int pix = pix0 + (q >> 1) * 8;
            float bias = (oc < 18) ? b_off[oc] : b_mod[oc - 18];
            float v = acc[ni][q] + bias;
            if (oc >= 18) v = 1.f / (1.f + __expf(-v));
            g_off[((size_t)b * NOC + oc) * HWSZ + (pix & 4095)] = v;
        }
    }
}

// ---------------- 3) bilinear sampling (fp16 src, 8 ch/thread) -----------
__global__ void __launch_bounds__(256) k_sample() {
    int tx  = threadIdx.x;                  // 0..15 channel octet
    int pos = blockIdx.x * 16 + threadIdx.y;
    int kk  = blockIdx.y;
    int b   = blockIdx.z;
    int h = pos >> 6, w = pos & 63;

    const float* offb = g_off + (b * NOC) * HWSZ;
    float dy = offb[(2 * kk)     * HWSZ + pos];
    float dx = offb[(2 * kk + 1) * HWSZ + pos];
    float m  = offb[(18 + kk)    * HWSZ + pos];

    float py = dy + (float)(h - 1 + kk / 3);
    float px = dx + (float)(w - 1 + kk % 3);
    float fy = floorf(py), fx = floorf(px);
    int y0 = (int)fy, x0 = (int)fx;
    float wy1 = py - fy, wx1 = px - fx;
    float wy0 = 1.f - wy1, wx0 = 1.f - wx1;

    const uint4* xb = (const uint4*)g_xTh + (size_t)(b * HWSZ) * 16;
    float acc[8];
    #pragma unroll
    for (int i = 0; i < 8; i++) acc[i] = 0.f;

    #pragma unroll
    for (int cn = 0; cn < 4; cn++) {
        int yi = y0 + (cn >> 1);
        int xi = x0 + (cn & 1);
        float wt = ((cn >> 1) ? wy1 : wy0) * ((cn & 1) ? wx1 : wx0);
        bool valid = (yi >= 0) & (yi < HH) & (xi >= 0) & (xi < WW);
        float wv = valid ? wt : 0.f;
        int yc = min(max(yi, 0), HH - 1);
        int xc = min(max(xi, 0), WW - 1);
        uint4 v = xb[(yc * WW + xc) * 16 + tx];
        __half2 h0 = *reinterpret_cast<__half2*>(&v.x);
        __half2 h1 = *reinterpret_cast<__half2*>(&v.y);
        __half2 h2 = *reinterpret_cast<__half2*>(&v.z);
        __half2 h3 = *reinterpret_cast<__half2*>(&v.w);
        float2 f0 = __half22float2(h0);
        float2 f1 = __half22float2(h1);
        float2 f2 = __half22float2(h2);
        float2 f3 = __half22float2(h3);
        acc[0] += wv * f0.x; acc[1] += wv * f0.y;
        acc[2] += wv * f1.x; acc[3] += wv * f1.y;
        acc[4] += wv * f2.x; acc[5] += wv * f2.y;
        acc[6] += wv * f3.x; acc[7] += wv * f3.y;
    }
    #pragma unroll
    for (int i = 0; i < 8; i++) acc[i] *= m;

    __half2 p0 = __floats2half2_rn(acc[0], acc[1]);
    __half2 p1 = __floats2half2_rn(acc[2], acc[3]);
    __half2 p2 = __floats2half2_rn(acc[4], acc[5]);
    __half2 p3 = __floats2half2_rn(acc[6], acc[7]);
    uint4 u;
    u.x = *reinterpret_cast<uint32_t*>(&p0);
    u.y = *reinterpret_cast<uint32_t*>(&p1);
    u.z = *reinterpret_cast<uint32_t*>(&p2);
    u.w = *reinterpret_cast<uint32_t*>(&p3);

    size_t e = ((size_t)(b * HWSZ) + pos) * CK + kk * 128 + tx * 8;
    *reinterpret_cast<uint4*>((char*)g_V + e * 2) = u;
}

// ---------------- 4) fp16 GEMM (m32n32, 3-stage, prefetch) + fp16 store ---
#define ROWB       80
#define A_BYTES    (64 * ROWB)         // 5120
#define B_BYTES    (128 * ROWB)        // 10240
#define STAGE_B    (A_BYTES + B_BYTES) // 15360
#define NSTG       3
#define GEMM_SMEM  (NSTG * STAGE_B)    // 46080
#define ROWSKIP    ((size_t)64 * CK * 2)   // 64-row global stride in bytes

__global__ void __launch_bounds__(256, 4) k_gemm_f16() {
    extern __shared__ __align__(128) char sm[];
    const uint32_t base = smem_u32(sm);
    const int tid  = threadIdx.x;
    const int lane = tid & 31;
    const int wid  = tid >> 5;
    const int rowBlk = blockIdx.x * 64;
    const int colBlk = blockIdx.y * 128;

    const int warpRow = (wid & 1) * 32;     // 2 m-warps (m32 each)
    const int warpCol = (wid >> 1) * 32;    // 4 n-warps (n32 each)
    const int lrow  = lane & 15;
    const int lhalf = (lane >> 4) * 16;

    const int ldrow = tid >> 2;             // 0..63
    const int ldcc  = (tid & 3) * 16;       // 0/16/32/48
    const char* pa = (const char*)g_V
        + ((size_t)(rowBlk + ldrow) * CK) * 2 + ldcc;
    const char* pb = (const char*)g_Wh
        + ((size_t)(colBlk + ldrow) * CK) * 2 + ldcc;
    const uint32_t dA = (uint32_t)ldrow * ROWB + ldcc;
    const uint32_t dB = A_BYTES + (uint32_t)ldrow * ROWB + ldcc;

    float acc[2][4][4];
    #pragma unroll
    for (int mi = 0; mi < 2; mi++)
        #pragma unroll
        for (int ni = 0; ni < 4; ni++)
            #pragma unroll
            for (int q = 0; q < 4; q++) acc[mi][ni][q] = 0.f;

    #pragma unroll
    for (int p = 0; p < 2; p++) {
        uint32_t buf = base + p * STAGE_B;
        cp16(buf + dA,                 pa);
        cp16(buf + dB,                 pb);
        cp16(buf + dB + 64 * ROWB,     pb + ROWSKIP);
        cp_commit();
        pa += 64; pb += 64;
    }

    int st = 0;
    for (int c = 0; c < 36; c++) {
        if (c + 1 < 36) cp_wait<1>(); else cp_wait<0>();
        __syncthreads();

        if (c + 2 < 36) {
            int nst = st + 2; if (nst >= NSTG) nst -= NSTG;
            uint32_t buf = base + nst * STAGE_B;
            cp16(buf + dA,             pa);
            cp16(buf + dB,             pb);
            cp16(buf + dB + 64 * ROWB, pb + ROWSKIP);
            cp_commit();
            pa += 64; pb += 64;
        }

        uint32_t bufA = base + st * STAGE_B;
        uint32_t bufB = bufA + A_BYTES;
        uint32_t arow0 = bufA + (uint32_t)(warpRow + lrow) * ROWB + lhalf;
        uint32_t brow0 = bufB + (uint32_t)(warpCol + lrow) * ROWB + lhalf;

        uint32_t a00[4], a01[4], a10[4], a11[4], b0[4], b1[4];
        ldm_x4(a00, arow0);
        ldm_x4(a01, arow0 + 16 * ROWB);
        ldm_x4(b0,  brow0);
        ldm_x4(b1,  brow0 + 16 * ROWB);
        ldm_x4(a10, arow0 + 32);
        ldm_x4(a11, arow0 + 16 * ROWB + 32);

        mma_f16(acc[0][0], a00, b0[0], b0[2]);
        mma_f16(acc[0][1], a00, b0[1], b0[3]);
        mma_f16(acc[0][2], a00, b1[0], b1[2]);
        mma_f16(acc[0][3], a00, b1[1], b1[3]);
        mma_f16(acc[1][0], a01, b0[0], b0[2]);
        mma_f16(acc[1][1], a01, b0[1], b0[3]);
        mma_f16(acc[1][2], a01, b1[0], b1[2]);
        mma_f16(acc[1][3], a01, b1[1], b1[3]);

        ldm_x4(b0, brow0 + 32);
        ldm_x4(b1, brow0 + 16 * ROWB + 32);
        mma_f16(acc[0][0], a10, b0[0], b0[2]);
        mma_f16(acc[0][1], a10, b0[1], b0[3]);
        mma_f16(acc[0][2], a10, b1[0], b1[2]);
        mma_f16(acc[0][3], a10, b1[1], b1[3]);
        mma_f16(acc[1][0], a11, b0[0], b0[2]);
        mma_f16(acc[1][1], a11, b0[1], b0[3]);
        mma_f16(acc[1][2], a11, b1[0], b1[2]);
        mma_f16(acc[1][3], a11, b1[1], b1[3]);

        st++; if (st >= NSTG) st = 0;
    }
    __syncthreads();

    // ---- store C as fp16 (half2 per 2 columns)
    #pragma unroll
    for (int mi = 0; mi < 2; mi++) {
        int r0 = rowBlk + warpRow + mi * 16 + lane / 4;
        #pragma unroll
        for (int ni = 0; ni < 4; ni++) {
            int c0 = colBlk + warpCol + ni * 8 + (lane & 3) * 2;
            __half2 h0 = __floats2half2_rn(acc[mi][ni][0], acc[mi][ni][1]);
            __half2 h1 = __floats2half2_rn(acc[mi][ni][2], acc[mi][ni][3]);
            *(__half2*)&g_outTh[(size_t)r0 * COUT + c0]       = h0;
            *(__half2*)&g_outTh[(size_t)(r0 + 8) * COUT + c0] = h1;
        }
    }

    // ---- fused BN partials (deterministic, fp32 accs)
    float* red_s  = (float*)sm;            // [8][32]
    float* red_ss = red_s + 8 * 32;        // [8][32]
    float sl[8], ssl[8];
    #pragma unroll
    for (int ni = 0; ni < 4; ni++) {
        #pragma unroll
        for (int j = 0; j < 2; j++) {
            float v0 = acc[0][ni][j], v1 = acc[0][ni][2 + j];
            float v2 = acc[1][ni][j], v3 = acc[1][ni][2 + j];
            sl [ni * 2 + j] = v0 + v1 + v2 + v3;
            ssl[ni * 2 + j] = v0 * v0 + v1 * v1 + v2 * v2 + v3 * v3;
        }
    }
    #pragma unroll
    for (int k = 0; k < 8; k++) {
        #pragma unroll
        for (int o = 4; o < 32; o <<= 1) {
            sl [k] += __shfl_down_sync(0xFFFFFFFFu, sl [k], o);
            ssl[k] += __shfl_down_sync(0xFFFFFFFFu, ssl[k], o);
        }
    }
    if (lane < 4) {
        #pragma unroll
        for (int ni = 0; ni < 4; ni++) {
            #pragma unroll
            for (int j = 0; j < 2; j++) {
                int cl = ni * 8 + lane * 2 + j;
                red_s [wid * 32 + cl] = sl [ni * 2 + j];
                red_ss[wid * 32 + cl] = ssl[ni * 2 + j];
            }
        }
    }
    __syncthreads();
    if (tid < 128) {
        int col = tid;
        int g   = col >> 5;
        int cl  = col & 31;
        float s  = red_s [(2 * g) * 32 + cl] + red_s [(2 * g + 1) * 32 + cl];
        float ss = red_ss[(2 * g) * 32 + cl] + red_ss[(2 * g + 1) * 32 + cl];
        int ch = colBlk + col;
        g_part[blockIdx.x * 512 + ch]       = s;
        g_part[blockIdx.x * 512 + 256 + ch] = ss;
    }
}

// ---------------- 5) BN reduction level 1 (32 blocks) ---------------------
__global__ void k_bn_lvl1() {
    int blk = blockIdx.x;          // 0..31, each sums 16 row-tiles
    int t = threadIdx.x;           // 0..255
    float s = 0.f, ss = 0.f;
    #pragma unroll
    for (int i = 0; i < 16; i++) {
        int r = blk * 16 + i;
        s  += g_part[r * 512 + t];
        ss += g_part[r * 512 + 256 + t];
    }
    g_part2[blk * 512 + t]       = s;
    g_part2[blk * 512 + 256 + t] = ss;
}

// ---------------- 6) finalize BN scale/shift -----------------------------
__global__ void k_bn_final(const float* __restrict__ gamma,
                           const float* __restrict__ beta) {
    int t = threadIdx.x;
    float s = 0.f, ss = 0.f;
    #pragma unroll
    for (int i = 0; i < 32; i++) {
        s  += g_part2[i * 512 + t];
        ss += g_part2[i * 512 + 256 + t];
    }
    const float invN = 1.f / 32768.f;
    float mean = s * invN;
    float var  = ss * invN - mean * mean;
    float inv  = rsqrtf(var + 1e-5f);
    float sc   = gamma[t] * inv;
    g_scale[t] = sc;
    g_shift[t] = beta[t] - mean * sc;
}

// ---------------- 7) affine + SiLU + transpose to NCHW -------------------
__global__ void k_epilogue(float* __restrict__ out) {
    __shared__ float tile[32][33];
    int tx = threadIdx.x, ty = threadIdx.y;
    int o0 = blockIdx.y * 32;
    int r0 = blockIdx.x * 32;
    int orq = o0 + tx;
    float sc = g_scale[orq], sh = g_shift[orq];
    #pragma unroll
    for (int j = 0; j < 4; j++) {
        int r = r0 + ty + j * 8;
        float v = __half2float(g_outTh[(size_t)r * COUT + orq]) * sc + sh;
        v = v / (1.f + __expf(-v));
        tile[ty + j * 8][tx] = v;
    }
    __syncthreads();
    int rw = r0 + tx;
    int bb = rw >> 12;
    int hw = rw & 4095;
    #pragma unroll
    for (int j = 0; j < 4; j++) {
        int o = o0 + ty + j * 8;
        out[((size_t)(bb * COUT + o)) * HWSZ + hw] = tile[tx][ty + j * 8];
    }
}

// ---------------- launch ---------------------------------------------------
extern "C" void kernel_launch(void* const* d_in, const int* in_sizes, int n_in,
                              void* d_out, int out_size) {
    const float* x     = (const float*)d_in[0];
    const float* w_off = (const float*)d_in[1];
    const float* b_off = (const float*)d_in[2];
    const float* w_mod = (const float*)d_in[3];
    const float* b_mod = (const float*)d_in[4];
    const float* w_dc  = (const float*)d_in[5];
    const float* gamma = (const float*)d_in[6];
    const float* beta  = (const float*)d_in[7];
    float* out = (float*)d_out;

    cudaFuncSetAttribute(k_conv_tc,  cudaFuncAttributeMaxDynamicSharedMemorySize, CONV_SMEM);
    cudaFuncSetAttribute(k_gemm_f16, cudaFuncAttributeMaxDynamicSharedMemorySize, GEMM_SMEM);

    k_prep<<<dim3(HWSZ / 32, CIN / 32, 9), dim3(32, 8)>>>(x, w_dc, w_off, w_mod);

    k_conv_tc<<<512, 256, CONV_SMEM>>>(b_off, b_mod);

    k_sample<<<dim3(HWSZ / 16, KK9, BATCH), dim3(16, 16)>>>();

    k_gemm_f16<<<dim3(ROWS / 64, 2), 256, GEMM_SMEM>>>();

    k_bn_lvl1<<<32, 256>>>();
    k_bn_final<<<1, 256>>>(gamma, beta);

    k_epilogue<<<dim3((BATCH * HWSZ) / 32, COUT / 32), dim3(32, 8)>>>(out);
}

// round 16
// speedup vs baseline: 1.1835x; 1.0002x over previous
#include <cuda_runtime.h>
#include <cuda_fp16.h>
#include <stdint.h>
#include <math.h>

// ---------------- problem constants ----------------
#define BATCH 8
#define CIN   128
#define COUT  256
#define HH    64
#define WW    64
#define HWSZ  4096
#define KK9   9
#define CK    1152          // CIN*KK9
#define NOC   27            // 18 offset + 9 modulation channels
#define ROWS  (BATCH*HWSZ)  // 32768

// ---------------- scratch ------------------------------------------------
__device__ __half g_xTh[BATCH * HWSZ * CIN];        // x channels-last fp16
__device__ float  g_off[BATCH * NOC * HWSZ];        // offsets + modulation(sigmoid)
__device__ __half g_Wch[32 * CK];                   // conv weights fp16, padded to 32 oc
__device__ __half g_Wh [COUT * CK];                 // deform weights fp16
__device__ __half g_V  [(size_t)ROWS * CK];         // sampled*mod fp16
__device__ __half g_outTh[(size_t)ROWS * COUT];     // GEMM result (fp16)
__device__ float  g_part [512 * 512];
__device__ float  g_part2[32 * 512];
__device__ float  g_scale[COUT];
__device__ float  g_shift[COUT];

// ---------------- ptx helpers (plain sm_80+ PTX only) --------------------
__device__ __forceinline__ uint32_t smem_u32(const void* p) {
    uint32_t a;
    asm("{ .reg .u64 t; cvta.to.shared.u64 t, %1; cvt.u32.u64 %0, t; }"
        : "=r"(a) : "l"(p));
    return a;
}
__device__ __forceinline__ void cp16(uint32_t dst, const void* src) {
    asm volatile("cp.async.cg.shared.global [%0], [%1], 16;" :: "r"(dst), "l"(src));
}
__device__ __forceinline__ void cp16z(uint32_t dst, const void* src, uint32_t sz) {
    asm volatile("cp.async.cg.shared.global [%0], [%1], 16, %2;"
                 :: "r"(dst), "l"(src), "r"(sz));
}
__device__ __forceinline__ void cp_commit() {
    asm volatile("cp.async.commit_group;" ::: "memory");
}
template <int N>
__device__ __forceinline__ void cp_wait() {
    asm volatile("cp.async.wait_group %0;" :: "n"(N) : "memory");
}
__device__ __forceinline__ void ldm_x4(uint32_t* r, uint32_t addr) {
    asm volatile("ldmatrix.sync.aligned.m8n8.x4.shared.b16 {%0,%1,%2,%3}, [%4];"
        : "=r"(r[0]), "=r"(r[1]), "=r"(r[2]), "=r"(r[3]) : "r"(addr));
}
__device__ __forceinline__ void mma_f16(float* d, const uint32_t* a,
                                        uint32_t b0, uint32_t b1) {
    asm volatile(
        "mma.sync.aligned.m16n8k16.row.col.f32.f16.f16.f32 "
        "{%0,%1,%2,%3}, {%4,%5,%6,%7}, {%8,%9}, {%0,%1,%2,%3};"
        : "+f"(d[0]), "+f"(d[1]), "+f"(d[2]), "+f"(d[3])
        : "r"(a[0]), "r"(a[1]), "r"(a[2]), "r"(a[3]), "r"(b0), "r"(b1));
}

// ---------------- 1) prep: transpose x -> fp16 channels-last + weights ---
__global__ void k_prep(const float* __restrict__ x,
                       const float* __restrict__ w_dc,
                       const float* __restrict__ w_off,
                       const float* __restrict__ w_mod) {
    if (blockIdx.z < 8) {
        __shared__ float tile[32][33];
        int b   = blockIdx.z;
        int hw0 = blockIdx.x * 32;
        int c0  = blockIdx.y * 32;
        int tx = threadIdx.x, ty = threadIdx.y;
        #pragma unroll
        for (int j = 0; j < 4; j++) {
            int c = c0 + ty + j * 8;
            tile[ty + j * 8][tx] = x[((b * CIN) + c) * HWSZ + hw0 + tx];
        }
        __syncthreads();
        #pragma unroll
        for (int j = 0; j < 4; j++) {
            int hw = hw0 + ty + j * 8;
            size_t o = ((size_t)(b * HWSZ) + hw) * CIN + c0 + tx;
            g_xTh[o] = __float2half(tile[tx][ty + j * 8]);
        }
    } else {
        const int NWP  = COUT * CK;         // 294912
        const int NWC2 = 32 * CK;           // 36864
        int t = threadIdx.y * 32 + threadIdx.x;
        int gidx = (blockIdx.y * 128 + blockIdx.x) * 256 + t;
        for (int idx = gidx; idx < NWP + NWC2; idx += 512 * 256) {
            if (idx < NWP) {
                int o  = idx / CK;
                int r  = idx - o * CK;
                int kk = r >> 7;
                int c  = r & 127;
                g_Wh[idx] = __float2half(w_dc[(o * CIN + c) * KK9 + kk]);
            } else {
                int j  = idx - NWP;
                int oc = j / CK;
                int r  = j - oc * CK;
                int kk = r >> 7;
                int c  = r & 127;
                float v = 0.f;
                if (oc < 18)      v = w_off[(oc * CIN + c) * KK9 + kk];
                else if (oc < 27) v = w_mod[((oc - 18) * CIN + c) * KK9 + kk];
                g_Wch[j] = __float2half(v);
            }
        }
    }
}

// ---------------- 2) conv offsets/mod via tensor cores (64-px tiles) -----
#define RCWB   80
#define A2_B   (64 * RCWB)                  // 5120
#define B2_B   (32 * RCWB)                  // 2560
#define CSTG   (A2_B + B2_B)                // 7680
#define CONV_SMEM (2 * CSTG)                // 15360

__device__ __forceinline__ void conv_load_stage(uint32_t buf, int cn,
                                                int rowBlk, int tid) {
    int kk  = cn >> 2;
    int c0k = (cn & 3) * 32;
    int dy = kk / 3 - 1;
    int dx = kk % 3 - 1;
    // A: 64 rows x 64B (256 cp16)
    {
        int row = tid >> 2;
        int cc  = tid & 3;
        int pix = rowBlk * 64 + row;
        int b = pix >> 12;
        int h = (pix >> 6) & 63;
        int w = pix & 63;
        int h2 = h + dy, w2 = w + dx;
        bool valid = ((unsigned)h2 < 64u) & ((unsigned)w2 < 64u);
        size_t srcoff = valid
            ? (((size_t)b * HWSZ + h2 * 64 + w2) * CIN + c0k) * 2 : 0;
        uint32_t sz = valid ? 16u : 0u;
        cp16z(buf + row * RCWB + cc * 16, (const char*)g_xTh + srcoff + cc * 16, sz);
    }
    // B: 32 rows x 64B (128 cp16)
    if (tid < 128) {
        int row = tid >> 2;
        int q   = tid & 3;
        const char* src = (const char*)g_Wch + ((size_t)row * CK + cn * 32) * 2 + q * 16;
        cp16(buf + A2_B + row * RCWB + q * 16, src);
    }
}

__global__ void __launch_bounds__(256) k_conv_tc(const float* __restrict__ b_off,
                                                 const float* __restrict__ b_mod) {
    extern __shared__ __align__(128) char sm[];
    const uint32_t base = smem_u32(sm);
    const int tid  = threadIdx.x;
    const int lane = tid & 31;
    const int wid  = tid >> 5;
    const int rowBlk = blockIdx.x;           // 512 tiles of 64 pixels

    const int warpRow = (wid & 3) * 16;      // 4 m-warps (m16)
    const int warpCol = (wid >> 2) * 16;     // 2 n-halves (n16)
    const int lrow  = lane & 15;
    const int lhalf = (lane >> 4) * 16;

    float acc[2][4];
    #pragma unroll
    for (int i = 0; i < 2; i++)
        #pragma unroll
        for (int q = 0; q < 4; q++) acc[i][q] = 0.f;

    conv_load_stage(base, 0, rowBlk, tid);
    cp_commit();

    for (int cn = 0; cn < 36; cn++) {
        int s = cn & 1;
        if (cn + 1 < 36) {
            conv_load_stage(base + ((cn + 1) & 1) * CSTG, cn + 1, rowBlk, tid);
            cp_commit();
            cp_wait<1>();
        } else {
            cp_wait<0>();
        }
        __syncthreads();

        uint32_t bufA = base + s * CSTG;
        uint32_t bufB = bufA + A2_B;

        #pragma unroll
        for (int ks = 0; ks < 2; ks++) {
            uint32_t a[4], bfr[4];
            ldm_x4(a,   bufA + (uint32_t)(warpRow + lrow) * RCWB + ks * 32 + lhalf);
            ldm_x4(bfr, bufB + (uint32_t)(warpCol + lrow) * RCWB + ks * 32 + lhalf);
            mma_f16(acc[0], a, bfr[0], bfr[2]);
            mma_f16(acc[1], a, bfr[1], bfr[3]);
        }
        __syncthreads();
    }

    int pix0 = rowBlk * 64 + warpRow + (lane >> 2);
    int b = pix0 >> 12;
    #pragma unroll
    for (int ni = 0; ni < 2; ni++) {
        #pragma unroll
        for (int q = 0; q < 4; q++) {
            int oc = warpCol + ni * 8 + (lane & 3) * 2 + (q & 1);
            if (oc >= NOC) continue;
            int pix = pix0 + (q >> 1) * 8;
            float bias = (oc < 18) ? b_off[oc] : b_mod[oc - 18];
            float v = acc[ni][q] + bias;
            if (oc >= 18) v = 1.f / (1.f + __expf(-v));
            g_off[((size_t)b * NOC + oc) * HWSZ + (pix & 4095)] = v;
        }
    }
}

// ---------------- 3) bilinear sampling (fp16 src, 16 ch/thread) ----------
__global__ void __launch_bounds__(256) k_sample() {
    int tx  = threadIdx.x;                  // 0..7 channel 16-group
    int pos = blockIdx.x * 32 + threadIdx.y;
    int kk  = blockIdx.y;
    int b   = blockIdx.z;
    int h = pos >> 6, w = pos & 63;

    const float* offb = g_off + (b * NOC) * HWSZ;
    float dy = offb[(2 * kk)     * HWSZ + pos];
    float dx = offb[(2 * kk + 1) * HWSZ + pos];
    float m  = offb[(18 + kk)    * HWSZ + pos];

    float py = dy + (float)(h - 1 + kk / 3);
    float px = dx + (float)(w - 1 + kk % 3);
    float fy = floorf(py), fx = floorf(px);
    int y0 = (int)fy, x0 = (int)fx;
    float wy1 = py - fy, wx1 = px - fx;
    float wy0 = 1.f - wy1, wx0 = 1.f - wx1;

    const uint4* xb = (const uint4*)g_xTh + (size_t)(b * HWSZ) * 16;
    float acc[16];
    #pragma unroll
    for (int i = 0; i < 16; i++) acc[i] = 0.f;

    #pragma unroll
    for (int cn = 0; cn < 4; cn++) {
        int yi = y0 + (cn >> 1);
        int xi = x0 + (cn & 1);
        float wt = ((cn >> 1) ? wy1 : wy0) * ((cn & 1) ? wx1 : wx0);
        bool valid = (yi >= 0) & (yi < HH) & (xi >= 0) & (xi < WW);
        float wv = valid ? wt : 0.f;
        int yc = min(max(yi, 0), HH - 1);
        int xc = min(max(xi, 0), WW - 1);
        const uint4* p = xb + (yc * WW + xc) * 16 + tx * 2;
        uint4 v0 = p[0];
        uint4 v1 = p[1];
        const uint32_t* vw = &v0.x;
        #pragma unroll
        for (int q = 0; q < 4; q++) {
            float2 f = __half22float2(*reinterpret_cast<const __half2*>(&vw[q]));
            acc[q * 2]     += wv * f.x;
            acc[q * 2 + 1] += wv * f.y;
        }
        const uint32_t* vw1 = &v1.x;
        #pragma unroll
        for (int q = 0; q < 4; q++) {
            float2 f = __half22float2(*reinterpret_cast<const __half2*>(&vw1[q]));
            acc[8 + q * 2]     += wv * f.x;
            acc[8 + q * 2 + 1] += wv * f.y;
        }
    }
    #pragma unroll
    for (int i = 0; i < 16; i++) acc[i] *= m;

    uint4 u0, u1;
    uint32_t* uw0 = &u0.x;
    uint32_t* uw1 = &u1.x;
    #pragma unroll
    for (int q = 0; q < 4; q++) {
        __half2 p0 = __floats2half2_rn(acc[q * 2],     acc[q * 2 + 1]);
        __half2 p1 = __floats2half2_rn(acc[8 + q * 2], acc[8 + q * 2 + 1]);
        uw0[q] = *reinterpret_cast<uint32_t*>(&p0);
        uw1[q] = *reinterpret_cast<uint32_t*>(&p1);
    }

    size_t e = ((size_t)(b * HWSZ) + pos) * CK + kk * 128 + tx * 16;
    uint4* dst = reinterpret_cast<uint4*>((char*)g_V + e * 2);
    dst[0] = u0;
    dst[1] = u1;
}

// ---------------- 4) fp16 GEMM (m32n32, 3-stage, prefetch) + fp16 store ---
#define ROWB       80
#define A_BYTES    (64 * ROWB)         // 5120
#define B_BYTES    (128 * ROWB)        // 10240
#define STAGE_B    (A_BYTES + B_BYTES) // 15360
#define NSTG       3
#define GEMM_SMEM  (NSTG * STAGE_B)    // 46080
#define ROWSKIP    ((size_t)64 * CK * 2)   // 64-row global stride in bytes

__global__ void __launch_bounds__(256, 4) k_gemm_f16() {
    extern __shared__ __align__(128) char sm[];
    const uint32_t base = smem_u32(sm);
    const int tid  = threadIdx.x;
    const int lane = tid & 31;
    const int wid  = tid >> 5;
    const int rowBlk = blockIdx.x * 64;
    const int colBlk = blockIdx.y * 128;

    const int warpRow = (wid & 1) * 32;     // 2 m-warps (m32 each)
    const int warpCol = (wid >> 1) * 32;    // 4 n-warps (n32 each)
    const int lrow  = lane & 15;
    const int lhalf = (lane >> 4) * 16;

    const int ldrow = tid >> 2;             // 0..63
    const int ldcc  = (tid & 3) * 16;       // 0/16/32/48
    const char* pa = (const char*)g_V
        + ((size_t)(rowBlk + ldrow) * CK) * 2 + ldcc;
    const char* pb = (const char*)g_Wh
        + ((size_t)(colBlk + ldrow) * CK) * 2 + ldcc;
    const uint32_t dA = (uint32_t)ldrow * ROWB + ldcc;
    const uint32_t dB = A_BYTES + (uint32_t)ldrow * ROWB + ldcc;

    float acc[2][4][4];
    #pragma unroll
    for (int mi = 0; mi < 2; mi++)
        #pragma unroll
        for (int ni = 0; ni < 4; ni++)
            #pragma unroll
            for (int q = 0; q < 4; q++) acc[mi][ni][q] = 0.f;

    #pragma unroll
    for (int p = 0; p < 2; p++) {
        uint32_t buf = base + p * STAGE_B;
        cp16(buf + dA,                 pa);
        cp16(buf + dB,                 pb);
        cp16(buf + dB + 64 * ROWB,     pb + ROWSKIP);
        cp_commit();
        pa += 64; pb += 64;
    }

    int st = 0;
    for (int c = 0; c < 36; c++) {
        if (c + 1 < 36) cp_wait<1>(); else cp_wait<0>();
        __syncthreads();

        if (c + 2 < 36) {
            int nst = st + 2; if (nst >= NSTG) nst -= NSTG;
            uint32_t buf = base + nst * STAGE_B;
            cp16(buf + dA,             pa);
            cp16(buf + dB,             pb);
            cp16(buf + dB + 64 * ROWB, pb + ROWSKIP);
            cp_commit();
            pa += 64; pb += 64;
        }

        uint32_t bufA = base + st * STAGE_B;
        uint32_t bufB = bufA + A_BYTES;
        uint32_t arow0 = bufA + (uint32_t)(warpRow + lrow) * ROWB + lhalf;
        uint32_t brow0 = bufB + (uint32_t)(warpCol + lrow) * ROWB + lhalf;

        uint32_t a00[4], a01[4], a10[4], a11[4], b0[4], b1[4];
        ldm_x4(a00, arow0);
        ldm_x4(a01, arow0 + 16 * ROWB);
        ldm_x4(b0,  brow0);
        ldm_x4(b1,  brow0 + 16 * ROWB);
        ldm_x4(a10, arow0 + 32);
        ldm_x4(a11, arow0 + 16 * ROWB + 32);

        mma_f16(acc[0][0], a00, b0[0], b0[2]);
        mma_f16(acc[0][1], a00, b0[1], b0[3]);
        mma_f16(acc[0][2], a00, b1[0], b1[2]);
        mma_f16(acc[0][3], a00, b1[1], b1[3]);
        mma_f16(acc[1][0], a01, b0[0], b0[2]);
        mma_f16(acc[1][1], a01, b0[1], b0[3]);
        mma_f16(acc[1][2], a01, b1[0], b1[2]);
        mma_f16(acc[1][3], a01, b1[1], b1[3]);

        ldm_x4(b0, brow0 + 32);
        ldm_x4(b1, brow0 + 16 * ROWB + 32);
        mma_f16(acc[0][0], a10, b0[0], b0[2]);
        mma_f16(acc[0][1], a10, b0[1], b0[3]);
        mma_f16(acc[0][2], a10, b1[0], b1[2]);
        mma_f16(acc[0][3], a10, b1[1], b1[3]);
        mma_f16(acc[1][0], a11, b0[0], b0[2]);
        mma_f16(acc[1][1], a11, b0[1], b0[3]);
        mma_f16(acc[1][2], a11, b1[0], b1[2]);
        mma_f16(acc[1][3], a11, b1[1], b1[3]);

        st++; if (st >= NSTG) st = 0;
    }
    __syncthreads();

    // ---- store C as fp16 (half2 per 2 columns)
    #pragma unroll
    for (int mi = 0; mi < 2; mi++) {
        int r0 = rowBlk + warpRow + mi * 16 + lane / 4;
        #pragma unroll
        for (int ni = 0; ni < 4; ni++) {
            int c0 = colBlk + warpCol + ni * 8 + (lane & 3) * 2;
            __half2 h0 = __floats2half2_rn(acc[mi][ni][0], acc[mi][ni][1]);
            __half2 h1 = __floats2half2_rn(acc[mi][ni][2], acc[mi][ni][3]);
            *(__half2*)&g_outTh[(size_t)r0 * COUT + c0]       = h0;
            *(__half2*)&g_outTh[(size_t)(r0 + 8) * COUT + c0] = h1;
        }
    }

    // ---- fused BN partials (deterministic, fp32 accs)
    float* red_s  = (float*)sm;            // [8][32]
    float* red_ss = red_s + 8 * 32;        // [8][32]
    float sl[8], ssl[8];
    #pragma unroll
    for (int ni = 0; ni < 4; ni++) {
        #pragma unroll
        for (int j = 0; j < 2; j++) {
            float v0 = acc[0][ni][j], v1 = acc[0][ni][2 + j];
            float v2 = acc[1][ni][j], v3 = acc[1][ni][2 + j];
            sl [ni * 2 + j] = v0 + v1 + v2 + v3;
            ssl[ni * 2 + j] = v0 * v0 + v1 * v1 + v2 * v2 + v3 * v3;
        }
    }
    #pragma unroll
    for (int k = 0; k < 8; k++) {
        #pragma unroll
        for (int o = 4; o < 32; o <<= 1) {
            sl [k] += __shfl_down_sync(0xFFFFFFFFu, sl [k], o);
            ssl[k] += __shfl_down_sync(0xFFFFFFFFu, ssl[k], o);
        }
    }
    if (lane < 4) {
        #pragma unroll
        for (int ni = 0; ni < 4; ni++) {
            #pragma unroll
            for (int j = 0; j < 2; j++) {
                int cl = ni * 8 + lane * 2 + j;
                red_s [wid * 32 + cl] = sl [ni * 2 + j];
                red_ss[wid * 32 + cl] = ssl[ni * 2 + j];
            }
        }
    }
    __syncthreads();
    if (tid < 128) {
        int col = tid;
        int g   = col >> 5;
        int cl  = col & 31;
        float s  = red_s [(2 * g) * 32 + cl] + red_s [(2 * g + 1) * 32 + cl];
        float ss = red_ss[(2 * g) * 32 + cl] + red_ss[(2 * g + 1) * 32 + cl];
        int ch = colBlk + col;
        g_part[blockIdx.x * 512 + ch]       = s;
        g_part[blockIdx.x * 512 + 256 + ch] = ss;
    }
}

// ---------------- 5) BN reduction level 1 (32 blocks) ---------------------
__global__ void k_bn_lvl1() {
    int blk = blockIdx.x;          // 0..31, each sums 16 row-tiles
    int t = threadIdx.x;           // 0..255
    float s = 0.f, ss = 0.f;
    #pragma unroll
    for (int i = 0; i < 16; i++) {
        int r = blk * 16 + i;
        s  += g_part[r * 512 + t];
        ss += g_part[r * 512 + 256 + t];
    }
    g_part2[blk * 512 + t]       = s;
    g_part2[blk * 512 + 256 + t] = ss;
}

// ---------------- 6) finalize BN scale/shift -----------------------------
__global__ void k_bn_final(const float* __restrict__ gamma,
                           const float* __restrict__ beta) {
    int t = threadIdx.x;
    float s = 0.f, ss = 0.f;
    #pragma unroll
    for (int i = 0; i < 32; i++) {
        s  += g_part2[i * 512 + t];
        ss += g_part2[i * 512 + 256 + t];
    }
    const float invN = 1.f / 32768.f;
    float mean = s * invN;
    float var  = ss * invN - mean * mean;
    float inv  = rsqrtf(var + 1e-5f);
    float sc   = gamma[t] * inv;
    g_scale[t] = sc;
    g_shift[t] = beta[t] - mean * sc;
}

// ---------------- 7) affine + SiLU + transpose to NCHW -------------------
__global__ void k_epilogue(float* __restrict__ out) {
    __shared__ float tile[32][33];
    int tx = threadIdx.x, ty = threadIdx.y;
    int o0 = blockIdx.y * 32;
    int r0 = blockIdx.x * 32;
    int orq = o0 + tx;
    float sc = g_scale[orq], sh = g_shift[orq];
    #pragma unroll
    for (int j = 0; j < 4; j++) {
        int r = r0 + ty + j * 8;
        float v = __half2float(g_outTh[(size_t)r * COUT + orq]) * sc + sh;
        v = v / (1.f + __expf(-v));
        tile[ty + j * 8][tx] = v;
    }
    __syncthreads();
    int rw = r0 + tx;
    int bb = rw >> 12;
    int hw = rw & 4095;
    #pragma unroll
    for (int j = 0; j < 4; j++) {
        int o = o0 + ty + j * 8;
        out[((size_t)(bb * COUT + o)) * HWSZ + hw] = tile[tx][ty + j * 8];
    }
}

// ---------------- launch ---------------------------------------------------
extern "C" void kernel_launch(void* const* d_in, const int* in_sizes, int n_in,
                              void* d_out, int out_size) {
    const float* x     = (const float*)d_in[0];
    const float* w_off = (const float*)d_in[1];
    const float* b_off = (const float*)d_in[2];
    const float* w_mod = (const float*)d_in[3];
    const float* b_mod = (const float*)d_in[4];
    const float* w_dc  = (const float*)d_in[5];
    const float* gamma = (const float*)d_in[6];
    const float* beta  = (const float*)d_in[7];
    float* out = (float*)d_out;

    cudaFuncSetAttribute(k_conv_tc,  cudaFuncAttributeMaxDynamicSharedMemorySize, CONV_SMEM);
    cudaFuncSetAttribute(k_gemm_f16, cudaFuncAttributeMaxDynamicSharedMemorySize, GEMM_SMEM);

    k_prep<<<dim3(HWSZ / 32, CIN / 32, 9), dim3(32, 8)>>>(x, w_dc, w_off, w_mod);

    k_conv_tc<<<512, 256, CONV_SMEM>>>(b_off, b_mod);

    k_sample<<<dim3(HWSZ / 32, KK9, BATCH), dim3(8, 32)>>>();

    k_gemm_f16<<<dim3(ROWS / 64, 2), 256, GEMM_SMEM>>>();

    k_bn_lvl1<<<32, 256>>>();
    k_bn_final<<<1, 256>>>(gamma, beta);

    k_epilogue<<<dim3((BATCH * HWSZ) / 32, COUT / 32), dim3(32, 8)>>>(out);
}